// round 11
// baseline (speedup 1.0000x reference)
#include <cuda_runtime.h>
#include <cuda_bf16.h>
#include <cstdint>

#define NH 32
#define NKV 8
#define SQ 2048
#define NBATCH 2
#define WIN 1024
#define SM_SCALE 0.08838834764831845f
#define EXC 0.12753785792920933f   // SM_SCALE * log2(e)
#define BM 128
#define BN 64
#define HD 128
#define THREADS 256

// ---- bf16 hi/lo scratch (filled by prep kernel once per launch) ----
#define KVELEMS (NBATCH * NKV * SQ * HD)
__device__ __align__(16) uint16_t KHIg[KVELEMS];
__device__ __align__(16) uint16_t KLOg[KVELEMS];
__device__ __align__(16) uint16_t VHIg[KVELEMS];
__device__ __align__(16) uint16_t VLOg[KVELEMS];

// smem layout (bytes)
#define QSTR 136
#define KSTR 136
#define VSTR 136
#define QHI_B 0
#define QLO_B (BM * QSTR * 2)
#define QREG  (2 * BM * QSTR * 2)              // 69632
#define ARRB  (BN * KSTR * 2)                  // 17408
#define BUFSZ (4 * ARRB)                       // 69632 (KHI,KLO,VHI,VLO)
#define KHI_O 0
#define VHI_O (2 * ARRB)
#define LO_OFF ARRB
#define SMEM_BYTES (QREG + 2 * BUFSZ + 16)

__device__ __forceinline__ uint32_t smaddr(const void* p) {
    uint32_t a;
    asm("{ .reg .u64 t; cvta.to.shared.u64 t, %1; cvt.u32.u64 %0, t; }" : "=r"(a) : "l"(p));
    return a;
}
__device__ __forceinline__ uint32_t packbf(float f0, float f1) {
    uint32_t d;
    asm("cvt.rn.bf16x2.f32 %0, %1, %2;" : "=r"(d) : "f"(f1), "f"(f0));
    return d;
}
__device__ __forceinline__ void split2(float f0, float f1, uint32_t& hi2, uint32_t& lo2) {
    hi2 = packbf(f0, f1);
    float h0 = __uint_as_float(hi2 << 16);
    float h1 = __uint_as_float(hi2 & 0xffff0000u);
    lo2 = packbf(f0 - h0, f1 - h1);
}
__device__ __forceinline__ float ex2f(float x) {
    float r; asm("ex2.approx.f32 %0, %1;" : "=f"(r) : "f"(x)); return r;
}
__device__ __forceinline__ void ldsm4(uint32_t a, uint32_t* r) {
    asm volatile("ldmatrix.sync.aligned.m8n8.x4.shared.b16 {%0,%1,%2,%3}, [%4];"
        : "=r"(r[0]), "=r"(r[1]), "=r"(r[2]), "=r"(r[3]) : "r"(a));
}
__device__ __forceinline__ void ldsm4t(uint32_t a, uint32_t* r) {
    asm volatile("ldmatrix.sync.aligned.m8n8.x4.trans.shared.b16 {%0,%1,%2,%3}, [%4];"
        : "=r"(r[0]), "=r"(r[1]), "=r"(r[2]), "=r"(r[3]) : "r"(a));
}
__device__ __forceinline__ void mma16816(float* c, const uint32_t* a, const uint32_t* b) {
    asm volatile("mma.sync.aligned.m16n8k16.row.col.f32.bf16.bf16.f32 "
        "{%0,%1,%2,%3}, {%4,%5,%6,%7}, {%8,%9}, {%0,%1,%2,%3};"
        : "+f"(c[0]), "+f"(c[1]), "+f"(c[2]), "+f"(c[3])
        : "r"(a[0]), "r"(a[1]), "r"(a[2]), "r"(a[3]), "r"(b[0]), "r"(b[1]));
}
__device__ __forceinline__ void cpa16(uint32_t saddr, const void* gaddr) {
    asm volatile("cp.async.cg.shared.global [%0], [%1], 16;" :: "r"(saddr), "l"(gaddr));
}
#define CP_COMMIT() asm volatile("cp.async.commit_group;" ::: "memory")
#define CP_WAIT0()  asm volatile("cp.async.wait_group 0;" ::: "memory")

// ---- prep: fp32 K/V -> bf16 hi/lo scratch, [b][hk][s][d] ----
__global__ __launch_bounds__(256)
void prep_kv(const float* __restrict__ Kg, const float* __restrict__ Vg)
{
    int i = blockIdx.x * blockDim.x + threadIdx.x;
    int d4 = (i & 31) << 2;
    int hk = (i >> 5) & 7;
    int s  = (i >> 8) & 2047;
    int b  = i >> 19;
    size_t in  = ((size_t)(b * SQ + s)) * (NKV * HD) + hk * HD + d4;
    size_t out = (((size_t)(b * NKV + hk)) * SQ + s) * HD + d4;

    float4 v = *(const float4*)(Kg + in);
    uint32_t h01, l01, h23, l23;
    split2(v.x, v.y, h01, l01);
    split2(v.z, v.w, h23, l23);
    *(uint2*)&KHIg[out] = make_uint2(h01, h23);
    *(uint2*)&KLOg[out] = make_uint2(l01, l23);

    float4 w = *(const float4*)(Vg + in);
    split2(w.x, w.y, h01, l01);
    split2(w.z, w.w, h23, l23);
    *(uint2*)&VHIg[out] = make_uint2(h01, h23);
    *(uint2*)&VLOg[out] = make_uint2(l01, l23);
}

__device__ __forceinline__ void issue_k(uint32_t sb, uint32_t buf, int tid, size_t kvrow0)
{
    const int ch8 = (tid & 15) * 8;
    #pragma unroll
    for (int i = 0; i < 8; i++) {
        const int arr = i >> 2;
        const int r = (i & 3) * 16 + (tid >> 4);
        const uint16_t* gb = arr ? KLOg : KHIg;
        cpa16(sb + buf + KHI_O + (uint32_t)arr * ARRB + (uint32_t)(r * KSTR + ch8) * 2u,
              gb + (kvrow0 + r) * HD + ch8);
    }
}
__device__ __forceinline__ void issue_v(uint32_t sb, uint32_t buf, int tid, size_t kvrow0)
{
    const int ch8 = (tid & 15) * 8;
    #pragma unroll
    for (int i = 0; i < 8; i++) {
        const int arr = i >> 2;
        const int r = (i & 3) * 16 + (tid >> 4);
        const uint16_t* gb = arr ? VLOg : VHIg;
        cpa16(sb + buf + VHI_O + (uint32_t)arr * ARRB + (uint32_t)(r * KSTR + ch8) * 2u,
              gb + (kvrow0 + r) * HD + ch8);
    }
}

// PV: P (regs) x V tile (x4 trans pairs) into oacc
__device__ __forceinline__ void pv_block(uint32_t va, const uint32_t phi[4][4],
                                         const uint32_t plo[4][4], float oacc[16][4])
{
    #pragma unroll
    for (int kb = 0; kb < 4; kb++) {
        #pragma unroll
        for (int np = 0; np < 8; np++) {
            uint32_t vh[4], vl[4];
            ldsm4t(va + kb * 4352 + np * 32, vh);
            ldsm4t(va + LO_OFF + kb * 4352 + np * 32, vl);
            mma16816(oacc[2 * np],     phi[kb], vh);
            mma16816(oacc[2 * np + 1], phi[kb], vh + 2);
            mma16816(oacc[2 * np],     phi[kb], vl);
            mma16816(oacc[2 * np + 1], phi[kb], vl + 2);
            mma16816(oacc[2 * np],     plo[kb], vh);
            mma16816(oacc[2 * np + 1], plo[kb], vh + 2);
        }
    }
}

__global__ __launch_bounds__(THREADS, 1)
void attn_hmma(const float* __restrict__ Qg, float* __restrict__ Og)
{
    extern __shared__ __align__(16) char smch[];
    const uint32_t sb = smaddr(smch);

    const int tid = threadIdx.x;
    const int wid = tid >> 5, lane = tid & 31;
    const int g = lane >> 2, tg = lane & 3;
    const int r0 = wid * 16;

    const int qt = blockIdx.x, h = blockIdx.y, b = blockIdx.z;
    const int hk = h >> 2;
    const int q0 = qt * BM;

    const float* Qb = Qg + ((size_t)b * SQ) * (NH * HD) + (size_t)h * HD;
    const size_t kvbase = ((size_t)(b * NKV + hk)) * SQ;

    // ---- Q tile -> smem hi/lo ----
    #pragma unroll
    for (int i = 0; i < 16; i++) {
        int c = tid + i * THREADS;
        int r = c >> 5, d4 = (c & 31) << 2;
        float4 v = *(const float4*)(Qb + (size_t)(q0 + r) * (NH * HD) + d4);
        uint32_t h01, l01, h23, l23;
        split2(v.x, v.y, h01, l01);
        split2(v.z, v.w, h23, l23);
        *(uint2*)(smch + QHI_B + (r * QSTR + d4) * 2) = make_uint2(h01, h23);
        *(uint2*)(smch + QLO_B + (r * QSTR + d4) * 2) = make_uint2(l01, l23);
    }

    const uint32_t qa = sb + QHI_B + ((r0 + (lane & 15)) * QSTR + ((lane >> 4) << 3)) * 2;
    const uint32_t ka_rel = (uint32_t)((((lane & 7) + ((lane >> 4) & 1) * 8) * KSTR
                                        + (((lane >> 3) & 1) << 3)) * 2);
    const uint32_t va_rel = (uint32_t)((lane & 15) * (VSTR * 2) + (((lane >> 4) & 1) << 4));

    float oacc[16][4];
    #pragma unroll
    for (int nb = 0; nb < 16; nb++)
        #pragma unroll
        for (int j = 0; j < 4; j++) oacc[nb][j] = 0.f;
    float lsum0 = 0.f, lsum1 = 0.f;
    uint32_t phi[4][4], plo[4][4];

    int lo_k = q0 - (WIN - 1); if (lo_k < 0) lo_k = 0;
    const int t0 = lo_k >> 6;
    const int t1 = (q0 + BM - 1) >> 6;

    // prologue: K(t0)
    issue_k(sb, QREG + (t0 & 1) * BUFSZ, tid, kvbase + ((size_t)t0 << 6));
    CP_COMMIT();

    for (int t = t0; t <= t1; ++t) {
        const int k0 = t << 6;

        CP_WAIT0();          // own copies of {K(t), V(t-1)} done
        __syncthreads();     // everyone's copies visible; prev-iter readers done

        // issue K(t+1) and V(t)
        if (t < t1)
            issue_k(sb, QREG + ((t + 1) & 1) * BUFSZ, tid, kvbase + ((size_t)(t + 1) << 6));
        issue_v(sb, QREG + (t & 1) * BUFSZ, tid, kvbase + ((size_t)t << 6));
        CP_COMMIT();

        // ---- PV(t-1): uses P in regs + V((t-1)&1) ----
        if (t > t0)
            pv_block(sb + QREG + ((t - 1) & 1) * BUFSZ + VHI_O + va_rel, phi, plo, oacc);

        // ---- QK^T(t): bf16x3 HMMA ----
        const uint32_t ka = sb + QREG + (t & 1) * BUFSZ + KHI_O + ka_rel;
        float sacc[8][4];
        #pragma unroll
        for (int nb = 0; nb < 8; nb++)
            #pragma unroll
            for (int j = 0; j < 4; j++) sacc[nb][j] = 0.f;

        #pragma unroll
        for (int kb = 0; kb < 8; kb++) {
            uint32_t ah[4], al[4];
            ldsm4(qa + kb * 32, ah);
            ldsm4(qa + (QLO_B - QHI_B) + kb * 32, al);
            #pragma unroll
            for (int np = 0; np < 4; np++) {
                uint32_t bh[4], bl[4];
                ldsm4(ka + np * 4352 + kb * 32, bh);
                ldsm4(ka + LO_OFF + np * 4352 + kb * 32, bl);
                mma16816(sacc[2 * np],     ah, bh);
                mma16816(sacc[2 * np + 1], ah, bh + 2);
                mma16816(sacc[2 * np],     ah, bl);
                mma16816(sacc[2 * np + 1], ah, bl + 2);
                mma16816(sacc[2 * np],     al, bh);
                mma16816(sacc[2 * np + 1], al, bh + 2);
            }
        }

        // ---- softmax(t) -> P hi/lo regs ----
        const bool allfull = (k0 + BN - 1 <= q0 + r0) && ((q0 + r0 + 15) - k0 < WIN);
        #pragma unroll
        for (int nb = 0; nb < 8; nb++) {
            float p[4];
            #pragma unroll
            for (int j = 0; j < 4; j++) {
                float pv = ex2f(sacc[nb][j] * EXC);
                if (!allfull) {
                    int key = k0 + nb * 8 + 2 * tg + (j & 1);
                    int row = q0 + r0 + g + ((j >> 1) << 3);
                    bool ok = (key <= row) && (row - key < WIN);
                    pv = ok ? pv : 0.f;
                }
                p[j] = pv;
            }
            lsum0 += p[0] + p[1];
            lsum1 += p[2] + p[3];
            int kb2 = nb >> 1, hi = nb & 1;
            split2(p[0], p[1], phi[kb2][hi * 2 + 0], plo[kb2][hi * 2 + 0]);
            split2(p[2], p[3], phi[kb2][hi * 2 + 1], plo[kb2][hi * 2 + 1]);
        }
    }

    // ---- epilogue PV(t1) ----
    CP_WAIT0();
    __syncthreads();
    pv_block(sb + QREG + (t1 & 1) * BUFSZ + VHI_O + va_rel, phi, plo, oacc);

    // ---- normalize + store ----
    lsum0 += __shfl_xor_sync(0xffffffffu, lsum0, 1);
    lsum0 += __shfl_xor_sync(0xffffffffu, lsum0, 2);
    lsum1 += __shfl_xor_sync(0xffffffffu, lsum1, 1);
    lsum1 += __shfl_xor_sync(0xffffffffu, lsum1, 2);
    const float inv0 = 1.f / lsum0;
    const float inv1 = 1.f / lsum1;

    const int row0 = q0 + r0 + g;
    float* o0 = Og + ((size_t)b * SQ + row0) * (NH * HD) + (size_t)h * HD;
    float* o1 = o0 + 8 * (size_t)(NH * HD);
    #pragma unroll
    for (int nb = 0; nb < 16; nb++) {
        int col = nb * 8 + 2 * tg;
        *(float2*)(o0 + col) = make_float2(oacc[nb][0] * inv0, oacc[nb][1] * inv0);
        *(float2*)(o1 + col) = make_float2(oacc[nb][2] * inv1, oacc[nb][3] * inv1);
    }
}

extern "C" void kernel_launch(void* const* d_in, const int* in_sizes, int n_in,
                              void* d_out, int out_size)
{
    const float* Q = (const float*)d_in[0];
    const float* K = (const float*)d_in[1];
    const float* V = (const float*)d_in[2];
    float* O = (float*)d_out;

    prep_kv<<<KVELEMS / 4 / 256, 256>>>(K, V);

    cudaFuncSetAttribute(attn_hmma, cudaFuncAttributeMaxDynamicSharedMemorySize, SMEM_BYTES);
    dim3 grid(SQ / BM, NH, NBATCH);
    attn_hmma<<<grid, THREADS, SMEM_BYTES>>>(Q, O);
}

// round 12
// speedup vs baseline: 1.0522x; 1.0522x over previous
#include <cuda_runtime.h>
#include <cuda_bf16.h>
#include <cstdint>

#define NH 32
#define NKV 8
#define SQ 2048
#define NBATCH 2
#define WIN 1024
#define SM_SCALE 0.08838834764831845f
#define BM 128
#define BN 64
#define HD 128
#define THREADS 256

// ---- bf16 hi/lo scratch (filled by prep kernel once per launch) ----
#define KVELEMS (NBATCH * NKV * SQ * HD)
__device__ __align__(16) uint16_t KHIg[KVELEMS];
__device__ __align__(16) uint16_t KLOg[KVELEMS];
__device__ __align__(16) uint16_t VHIg[KVELEMS];
__device__ __align__(16) uint16_t VLOg[KVELEMS];

// smem layout (bytes): Q hi/lo static; K/V hi/lo double-buffered
#define QSTR 136
#define KSTR 136
#define VSTR 136
#define QHI_B 0
#define QLO_B (BM * QSTR * 2)                  // 34816
#define QREG  (2 * BM * QSTR * 2)              // 69632
#define ARRB  (BN * KSTR * 2)                  // 17408 per array
#define BUFSZ (4 * ARRB)                       // 69632 per buffer
#define KHI_O 0
#define KLO_O ARRB
#define VHI_O (2 * ARRB)
#define VLO_O (3 * ARRB)
#define LO_OFF ARRB
#define SMEM_BYTES (QREG + 2 * BUFSZ + 16)     // ~204 KB

__device__ __forceinline__ uint32_t smaddr(const void* p) {
    uint32_t a;
    asm("{ .reg .u64 t; cvta.to.shared.u64 t, %1; cvt.u32.u64 %0, t; }" : "=r"(a) : "l"(p));
    return a;
}
__device__ __forceinline__ uint32_t packbf(float f0, float f1) {
    uint32_t d;
    asm("cvt.rn.bf16x2.f32 %0, %1, %2;" : "=r"(d) : "f"(f1), "f"(f0));
    return d;
}
__device__ __forceinline__ void split2(float f0, float f1, uint32_t& hi2, uint32_t& lo2) {
    hi2 = packbf(f0, f1);
    float h0 = __uint_as_float(hi2 << 16);
    float h1 = __uint_as_float(hi2 & 0xffff0000u);
    lo2 = packbf(f0 - h0, f1 - h1);
}
__device__ __forceinline__ void ldsm4(uint32_t a, uint32_t* r) {
    asm volatile("ldmatrix.sync.aligned.m8n8.x4.shared.b16 {%0,%1,%2,%3}, [%4];"
        : "=r"(r[0]), "=r"(r[1]), "=r"(r[2]), "=r"(r[3]) : "r"(a));
}
__device__ __forceinline__ void ldsm4t(uint32_t a, uint32_t* r) {
    asm volatile("ldmatrix.sync.aligned.m8n8.x4.trans.shared.b16 {%0,%1,%2,%3}, [%4];"
        : "=r"(r[0]), "=r"(r[1]), "=r"(r[2]), "=r"(r[3]) : "r"(a));
}
__device__ __forceinline__ void mma16816(float* c, const uint32_t* a, const uint32_t* b) {
    asm volatile("mma.sync.aligned.m16n8k16.row.col.f32.bf16.bf16.f32 "
        "{%0,%1,%2,%3}, {%4,%5,%6,%7}, {%8,%9}, {%0,%1,%2,%3};"
        : "+f"(c[0]), "+f"(c[1]), "+f"(c[2]), "+f"(c[3])
        : "r"(a[0]), "r"(a[1]), "r"(a[2]), "r"(a[3]), "r"(b[0]), "r"(b[1]));
}
__device__ __forceinline__ void cpa16(uint32_t saddr, const void* gaddr) {
    asm volatile("cp.async.cg.shared.global [%0], [%1], 16;" :: "r"(saddr), "l"(gaddr));
}

// ---- prep: fp32 K/V -> bf16 hi/lo scratch, [b][hk][s][d] layout ----
__global__ __launch_bounds__(256)
void prep_kv(const float* __restrict__ Kg, const float* __restrict__ Vg)
{
    int i = blockIdx.x * blockDim.x + threadIdx.x;
    int d4 = (i & 31) << 2;
    int hk = (i >> 5) & 7;
    int s  = (i >> 8) & 2047;
    int b  = i >> 19;
    size_t in  = ((size_t)(b * SQ + s)) * (NKV * HD) + hk * HD + d4;
    size_t out = (((size_t)(b * NKV + hk)) * SQ + s) * HD + d4;

    float4 v = *(const float4*)(Kg + in);
    uint32_t h01, l01, h23, l23;
    split2(v.x, v.y, h01, l01);
    split2(v.z, v.w, h23, l23);
    *(uint2*)&KHIg[out] = make_uint2(h01, h23);
    *(uint2*)&KLOg[out] = make_uint2(l01, l23);

    float4 w = *(const float4*)(Vg + in);
    split2(w.x, w.y, h01, l01);
    split2(w.z, w.w, h23, l23);
    *(uint2*)&VHIg[out] = make_uint2(h01, h23);
    *(uint2*)&VLOg[out] = make_uint2(l01, l23);
}

// issue 16B cp.async chunks for one 64-row tile (all 4 arrays) into buf
__device__ __forceinline__ void issue_tile(uint32_t sb, uint32_t buf, int tid,
                                           size_t kvrow0)
{
    const int ch8 = (tid & 15) * 8;
    #pragma unroll
    for (int i = 0; i < 16; i++) {
        const int arr = i >> 2;
        const int r = ((i * 16) + (tid >> 4)) & 63;
        const uint16_t* gb = (arr == 0) ? KHIg : (arr == 1) ? KLOg
                           : (arr == 2) ? VHIg : VLOg;
        const void* g = gb + (kvrow0 + r) * HD + ch8;
        uint32_t s = sb + buf + (uint32_t)arr * ARRB + (uint32_t)(r * KSTR + ch8) * 2u;
        cpa16(s, g);
    }
}

__global__ __launch_bounds__(THREADS, 1)
void attn_hmma(const float* __restrict__ Qg, float* __restrict__ Og)
{
    extern __shared__ __align__(16) char smch[];
    const uint32_t sb = smaddr(smch);

    const int tid = threadIdx.x;
    const int wid = tid >> 5, lane = tid & 31;
    const int g = lane >> 2, tg = lane & 3;
    const int r0 = wid * 16;

    const int qt = blockIdx.x, h = blockIdx.y, b = blockIdx.z;
    const int hk = h >> 2;
    const int q0 = qt * BM;

    const float* Qb = Qg + ((size_t)b * SQ) * (NH * HD) + (size_t)h * HD;
    const size_t kvbase = ((size_t)(b * NKV + hk)) * SQ;

    // ---- Q tile -> smem hi/lo ----
    #pragma unroll
    for (int i = 0; i < 16; i++) {
        int c = tid + i * THREADS;
        int r = c >> 5, d4 = (c & 31) << 2;
        float4 v = *(const float4*)(Qb + (size_t)(q0 + r) * (NH * HD) + d4);
        uint32_t h01, l01, h23, l23;
        split2(v.x, v.y, h01, l01);
        split2(v.z, v.w, h23, l23);
        *(uint2*)(smch + QHI_B + (r * QSTR + d4) * 2) = make_uint2(h01, h23);
        *(uint2*)(smch + QLO_B + (r * QSTR + d4) * 2) = make_uint2(l01, l23);
    }

    // per-thread ldmatrix addrs (x4 pairings)
    const uint32_t qa = sb + QHI_B + ((r0 + (lane & 15)) * QSTR + ((lane >> 4) << 3)) * 2;
    const uint32_t ka_rel = (uint32_t)((((lane & 7) + ((lane >> 4) & 1) * 8) * KSTR
                                        + (((lane >> 3) & 1) << 3)) * 2);
    const uint32_t va_rel = (uint32_t)((lane & 15) * (VSTR * 2) + (((lane >> 4) & 1) << 4));

    float oacc[16][4];
    #pragma unroll
    for (int nb = 0; nb < 16; nb++)
        #pragma unroll
        for (int j = 0; j < 4; j++) oacc[nb][j] = 0.f;
    float lsum0 = 0.f, lsum1 = 0.f;

    int lo_k = q0 - (WIN - 1); if (lo_k < 0) lo_k = 0;
    const int t0 = lo_k >> 6;
    const int t1 = (q0 + BM - 1) >> 6;

    issue_tile(sb, QREG, tid, kvbase + ((size_t)t0 << 6));
    asm volatile("cp.async.commit_group;" ::: "memory");

    for (int t = t0; t <= t1; ++t) {
        const int k0 = t << 6;
        const uint32_t bufc = QREG + ((t - t0) & 1) * BUFSZ;
        const uint32_t bufn = QREG + (((t - t0) + 1) & 1) * BUFSZ;

        if (t < t1)
            issue_tile(sb, bufn, tid, kvbase + ((size_t)(t + 1) << 6));
        asm volatile("cp.async.commit_group;" ::: "memory");
        asm volatile("cp.async.wait_group 1;" ::: "memory");
        __syncthreads();

        // ---- QK^T: bf16x3 HMMA, term-grouped (chain distance 8) ----
        const uint32_t ka = sb + bufc + KHI_O + ka_rel;
        float sacc[8][4];
        #pragma unroll
        for (int nb = 0; nb < 8; nb++)
            #pragma unroll
            for (int j = 0; j < 4; j++) sacc[nb][j] = 0.f;

        #pragma unroll
        for (int kb = 0; kb < 8; kb++) {
            uint32_t ah[4], al[4];
            ldsm4(qa + kb * 32, ah);
            ldsm4(qa + (QLO_B - QHI_B) + kb * 32, al);
            uint32_t bh[4][4], bl[4][4];
            #pragma unroll
            for (int np = 0; np < 4; np++) {
                ldsm4(ka + np * 4352 + kb * 32, bh[np]);
                ldsm4(ka + LO_OFF + np * 4352 + kb * 32, bl[np]);
            }
            #pragma unroll
            for (int np = 0; np < 4; np++) {
                mma16816(sacc[2 * np],     ah, bh[np]);
                mma16816(sacc[2 * np + 1], ah, bh[np] + 2);
            }
            #pragma unroll
            for (int np = 0; np < 4; np++) {
                mma16816(sacc[2 * np],     ah, bl[np]);
                mma16816(sacc[2 * np + 1], ah, bl[np] + 2);
            }
            #pragma unroll
            for (int np = 0; np < 4; np++) {
                mma16816(sacc[2 * np],     al, bh[np]);
                mma16816(sacc[2 * np + 1], al, bh[np] + 2);
            }
        }

        // ---- softmax (no max-shift) + P hi/lo A-fragments ----
        uint32_t phi[4][4], plo[4][4];
        const bool allfull = (k0 + BN - 1 <= q0 + r0) && ((q0 + r0 + 15) - k0 < WIN);
        #pragma unroll
        for (int nb = 0; nb < 8; nb++) {
            float p[4];
            #pragma unroll
            for (int j = 0; j < 4; j++) {
                float pv = __expf(sacc[nb][j] * SM_SCALE);
                if (!allfull) {
                    int key = k0 + nb * 8 + 2 * tg + (j & 1);
                    int row = q0 + r0 + g + ((j >> 1) << 3);
                    bool ok = (key <= row) && (row - key < WIN);
                    pv = ok ? pv : 0.f;
                }
                p[j] = pv;
            }
            lsum0 += p[0] + p[1];
            lsum1 += p[2] + p[3];
            int kb2 = nb >> 1, hi = nb & 1;
            split2(p[0], p[1], phi[kb2][hi * 2 + 0], plo[kb2][hi * 2 + 0]);
            split2(p[2], p[3], phi[kb2][hi * 2 + 1], plo[kb2][hi * 2 + 1]);
        }

        // ---- PV: term-grouped over V column pairs (chain distance 4) ----
        const uint32_t va = sb + bufc + VHI_O + va_rel;
        #pragma unroll
        for (int kb = 0; kb < 4; kb++) {
            #pragma unroll
            for (int npp = 0; npp < 4; npp++) {
                uint32_t vh0[4], vl0[4], vh1[4], vl1[4];
                ldsm4t(va + kb * 4352 + (2 * npp) * 32, vh0);
                ldsm4t(va + LO_OFF + kb * 4352 + (2 * npp) * 32, vl0);
                ldsm4t(va + kb * 4352 + (2 * npp + 1) * 32, vh1);
                ldsm4t(va + LO_OFF + kb * 4352 + (2 * npp + 1) * 32, vl1);
                float* o0 = oacc[4 * npp + 0];
                float* o1 = oacc[4 * npp + 1];
                float* o2 = oacc[4 * npp + 2];
                float* o3 = oacc[4 * npp + 3];
                mma16816(o0, phi[kb], vh0);
                mma16816(o1, phi[kb], vh0 + 2);
                mma16816(o2, phi[kb], vh1);
                mma16816(o3, phi[kb], vh1 + 2);
                mma16816(o0, phi[kb], vl0);
                mma16816(o1, phi[kb], vl0 + 2);
                mma16816(o2, phi[kb], vl1);
                mma16816(o3, phi[kb], vl1 + 2);
                mma16816(o0, plo[kb], vh0);
                mma16816(o1, plo[kb], vh0 + 2);
                mma16816(o2, plo[kb], vh1);
                mma16816(o3, plo[kb], vh1 + 2);
            }
        }
        __syncthreads();
    }

    // ---- normalize + store ----
    lsum0 += __shfl_xor_sync(0xffffffffu, lsum0, 1);
    lsum0 += __shfl_xor_sync(0xffffffffu, lsum0, 2);
    lsum1 += __shfl_xor_sync(0xffffffffu, lsum1, 1);
    lsum1 += __shfl_xor_sync(0xffffffffu, lsum1, 2);
    const float inv0 = 1.f / lsum0;
    const float inv1 = 1.f / lsum1;

    const int row0 = q0 + r0 + g;
    float* o0 = Og + ((size_t)b * SQ + row0) * (NH * HD) + (size_t)h * HD;
    float* o1 = o0 + 8 * (size_t)(NH * HD);
    #pragma unroll
    for (int nb = 0; nb < 16; nb++) {
        int col = nb * 8 + 2 * tg;
        *(float2*)(o0 + col) = make_float2(oacc[nb][0] * inv0, oacc[nb][1] * inv0);
        *(float2*)(o1 + col) = make_float2(oacc[nb][2] * inv1, oacc[nb][3] * inv1);
    }
}

extern "C" void kernel_launch(void* const* d_in, const int* in_sizes, int n_in,
                              void* d_out, int out_size)
{
    const float* Q = (const float*)d_in[0];
    const float* K = (const float*)d_in[1];
    const float* V = (const float*)d_in[2];
    float* O = (float*)d_out;

    prep_kv<<<KVELEMS / 4 / 256, 256>>>(K, V);

    cudaFuncSetAttribute(attn_hmma, cudaFuncAttributeMaxDynamicSharedMemorySize, SMEM_BYTES);
    dim3 grid(SQ / BM, NH, NBATCH);
    attn_hmma<<<grid, THREADS, SMEM_BYTES>>>(Q, O);
}

// round 13
// speedup vs baseline: 1.1009x; 1.0463x over previous
#include <cuda_runtime.h>
#include <cuda_fp16.h>
#include <cstdint>

#define NH 32
#define NKV 8
#define SQ 2048
#define NBATCH 2
#define WIN 1024
#define SM_SCALE 0.08838834764831845f
#define BM 128
#define BN 64
#define HD 128
#define THREADS 256

// ---- fp16 hi/lo scratch (filled by prep kernel once per launch) ----
#define KVELEMS (NBATCH * NKV * SQ * HD)
__device__ __align__(16) uint16_t KHIg[KVELEMS];
__device__ __align__(16) uint16_t KLOg[KVELEMS];
__device__ __align__(16) uint16_t VHIg[KVELEMS];
__device__ __align__(16) uint16_t VLOg[KVELEMS];

// smem layout (bytes): Q hi static; K/V hi/lo double-buffered
#define QSTR 136
#define KSTR 136
#define VSTR 136
#define QHI_B 0
#define QREG  (BM * QSTR * 2)                  // 34816 (no Q-lo needed)
#define ARRB  (BN * KSTR * 2)                  // 17408 per array
#define BUFSZ (4 * ARRB)                       // 69632 per buffer
#define KHI_O 0
#define VHI_O (2 * ARRB)
#define LO_OFF ARRB
#define SMEM_BYTES (QREG + 2 * BUFSZ + 16)     // ~170 KB

__device__ __forceinline__ uint32_t smaddr(const void* p) {
    uint32_t a;
    asm("{ .reg .u64 t; cvta.to.shared.u64 t, %1; cvt.u32.u64 %0, t; }" : "=r"(a) : "l"(p));
    return a;
}
__device__ __forceinline__ uint32_t packh2(float f0, float f1) {
    __half2 h = __floats2half2_rn(f0, f1);
    return *(uint32_t*)&h;
}
__device__ __forceinline__ void split2h(float f0, float f1, uint32_t& hi2, uint32_t& lo2) {
    __half2 h = __floats2half2_rn(f0, f1);
    hi2 = *(uint32_t*)&h;
    float2 back = __half22float2(h);
    __half2 l = __floats2half2_rn(f0 - back.x, f1 - back.y);
    lo2 = *(uint32_t*)&l;
}
__device__ __forceinline__ void ldsm4(uint32_t a, uint32_t* r) {
    asm volatile("ldmatrix.sync.aligned.m8n8.x4.shared.b16 {%0,%1,%2,%3}, [%4];"
        : "=r"(r[0]), "=r"(r[1]), "=r"(r[2]), "=r"(r[3]) : "r"(a));
}
__device__ __forceinline__ void ldsm4t(uint32_t a, uint32_t* r) {
    asm volatile("ldmatrix.sync.aligned.m8n8.x4.trans.shared.b16 {%0,%1,%2,%3}, [%4];"
        : "=r"(r[0]), "=r"(r[1]), "=r"(r[2]), "=r"(r[3]) : "r"(a));
}
__device__ __forceinline__ void mma_f16(float* c, const uint32_t* a, const uint32_t* b) {
    asm volatile("mma.sync.aligned.m16n8k16.row.col.f32.f16.f16.f32 "
        "{%0,%1,%2,%3}, {%4,%5,%6,%7}, {%8,%9}, {%0,%1,%2,%3};"
        : "+f"(c[0]), "+f"(c[1]), "+f"(c[2]), "+f"(c[3])
        : "r"(a[0]), "r"(a[1]), "r"(a[2]), "r"(a[3]), "r"(b[0]), "r"(b[1]));
}
__device__ __forceinline__ void cpa16(uint32_t saddr, const void* gaddr) {
    asm volatile("cp.async.cg.shared.global [%0], [%1], 16;" :: "r"(saddr), "l"(gaddr));
}

// ---- prep: fp32 K/V -> fp16 hi/lo scratch, [b][hk][s][d] layout ----
__global__ __launch_bounds__(256)
void prep_kv(const float* __restrict__ Kg, const float* __restrict__ Vg)
{
    int i = blockIdx.x * blockDim.x + threadIdx.x;
    int d4 = (i & 31) << 2;
    int hk = (i >> 5) & 7;
    int s  = (i >> 8) & 2047;
    int b  = i >> 19;
    size_t in  = ((size_t)(b * SQ + s)) * (NKV * HD) + hk * HD + d4;
    size_t out = (((size_t)(b * NKV + hk)) * SQ + s) * HD + d4;

    float4 v = *(const float4*)(Kg + in);
    uint32_t h01, l01, h23, l23;
    split2h(v.x, v.y, h01, l01);
    split2h(v.z, v.w, h23, l23);
    *(uint2*)&KHIg[out] = make_uint2(h01, h23);
    *(uint2*)&KLOg[out] = make_uint2(l01, l23);

    float4 w = *(const float4*)(Vg + in);
    split2h(w.x, w.y, h01, l01);
    split2h(w.z, w.w, h23, l23);
    *(uint2*)&VHIg[out] = make_uint2(h01, h23);
    *(uint2*)&VLOg[out] = make_uint2(l01, l23);
}

// issue 16B cp.async chunks for one 64-row tile (all 4 arrays) into buf
__device__ __forceinline__ void issue_tile(uint32_t sb, uint32_t buf, int tid,
                                           size_t kvrow0)
{
    const int ch8 = (tid & 15) * 8;
    #pragma unroll
    for (int i = 0; i < 16; i++) {
        const int arr = i >> 2;
        const int r = ((i * 16) + (tid >> 4)) & 63;
        const uint16_t* gb = (arr == 0) ? KHIg : (arr == 1) ? KLOg
                           : (arr == 2) ? VHIg : VLOg;
        const void* g = gb + (kvrow0 + r) * HD + ch8;
        uint32_t s = sb + buf + (uint32_t)arr * ARRB + (uint32_t)(r * KSTR + ch8) * 2u;
        cpa16(s, g);
    }
}

__global__ __launch_bounds__(THREADS, 1)
void attn_hmma(const float* __restrict__ Qg, float* __restrict__ Og)
{
    extern __shared__ __align__(16) char smch[];
    const uint32_t sb = smaddr(smch);

    const int tid = threadIdx.x;
    const int wid = tid >> 5, lane = tid & 31;
    const int g = lane >> 2, tg = lane & 3;
    const int r0 = wid * 16;

    const int qt = blockIdx.x, h = blockIdx.y, b = blockIdx.z;
    const int hk = h >> 2;
    const int q0 = qt * BM;

    const float* Qb = Qg + ((size_t)b * SQ) * (NH * HD) + (size_t)h * HD;
    const size_t kvbase = ((size_t)(b * NKV + hk)) * SQ;

    // ---- Q tile -> smem (fp16 hi only; lo term dropped in 2-term QK) ----
    #pragma unroll
    for (int i = 0; i < 16; i++) {
        int c = tid + i * THREADS;
        int r = c >> 5, d4 = (c & 31) << 2;
        float4 v = *(const float4*)(Qb + (size_t)(q0 + r) * (NH * HD) + d4);
        uint32_t h01 = packh2(v.x, v.y);
        uint32_t h23 = packh2(v.z, v.w);
        *(uint2*)(smch + QHI_B + (r * QSTR + d4) * 2) = make_uint2(h01, h23);
    }

    // per-thread ldmatrix addrs (x4 pairings)
    const uint32_t qa = sb + QHI_B + ((r0 + (lane & 15)) * QSTR + ((lane >> 4) << 3)) * 2;
    const uint32_t ka_rel = (uint32_t)((((lane & 7) + ((lane >> 4) & 1) * 8) * KSTR
                                        + (((lane >> 3) & 1) << 3)) * 2);
    const uint32_t va_rel = (uint32_t)((lane & 15) * (VSTR * 2) + (((lane >> 4) & 1) << 4));

    float oacc[16][4];
    #pragma unroll
    for (int nb = 0; nb < 16; nb++)
        #pragma unroll
        for (int j = 0; j < 4; j++) oacc[nb][j] = 0.f;
    float lsum0 = 0.f, lsum1 = 0.f;

    int lo_k = q0 - (WIN - 1); if (lo_k < 0) lo_k = 0;
    const int t0 = lo_k >> 6;
    const int t1 = (q0 + BM - 1) >> 6;

    issue_tile(sb, QREG, tid, kvbase + ((size_t)t0 << 6));
    asm volatile("cp.async.commit_group;" ::: "memory");

    for (int t = t0; t <= t1; ++t) {
        const int k0 = t << 6;
        const uint32_t bufc = QREG + ((t - t0) & 1) * BUFSZ;
        const uint32_t bufn = QREG + (((t - t0) + 1) & 1) * BUFSZ;

        if (t < t1)
            issue_tile(sb, bufn, tid, kvbase + ((size_t)(t + 1) << 6));
        asm volatile("cp.async.commit_group;" ::: "memory");
        asm volatile("cp.async.wait_group 1;" ::: "memory");
        __syncthreads();

        const uint32_t ka = sb + bufc + KHI_O + ka_rel;
        const uint32_t va = sb + bufc + VHI_O + va_rel;
        const bool allfull = (k0 + BN - 1 <= q0 + r0) && ((q0 + r0 + 15) - k0 < WIN);

        float sacc[8][4];
        #pragma unroll
        for (int nb = 0; nb < 8; nb++)
            #pragma unroll
            for (int j = 0; j < 4; j++) sacc[nb][j] = 0.f;

        uint32_t phi[4][4], plo[4][4];

        // ============ QK-A: keys 0..31 (np 0,1), fp16 2-term ============
        #pragma unroll
        for (int kb = 0; kb < 8; kb++) {
            uint32_t ah[4];
            ldsm4(qa + kb * 32, ah);
            #pragma unroll
            for (int np = 0; np < 2; np++) {
                uint32_t bh[4], bl[4];
                ldsm4(ka + np * 4352 + kb * 32, bh);
                ldsm4(ka + LO_OFF + np * 4352 + kb * 32, bl);
                mma_f16(sacc[2 * np],     ah, bh);
                mma_f16(sacc[2 * np + 1], ah, bh + 2);
                mma_f16(sacc[2 * np],     ah, bl);
                mma_f16(sacc[2 * np + 1], ah, bl + 2);
            }
        }

        // ============ softmax-A (nb 0..3) ============
        #pragma unroll
        for (int nb = 0; nb < 4; nb++) {
            float p[4];
            #pragma unroll
            for (int j = 0; j < 4; j++) {
                float pv = __expf(sacc[nb][j] * SM_SCALE);
                if (!allfull) {
                    int key = k0 + nb * 8 + 2 * tg + (j & 1);
                    int row = q0 + r0 + g + ((j >> 1) << 3);
                    bool ok = (key <= row) && (row - key < WIN);
                    pv = ok ? pv : 0.f;
                }
                p[j] = pv;
            }
            lsum0 += p[0] + p[1];
            lsum1 += p[2] + p[3];
            int kb2 = nb >> 1, hi = nb & 1;
            split2h(p[0], p[1], phi[kb2][hi * 2 + 0], plo[kb2][hi * 2 + 0]);
            split2h(p[2], p[3], phi[kb2][hi * 2 + 1], plo[kb2][hi * 2 + 1]);
        }

        // ============ QK-B: keys 32..63 (np 2,3) ============
        #pragma unroll
        for (int kb = 0; kb < 8; kb++) {
            uint32_t ah[4];
            ldsm4(qa + kb * 32, ah);
            #pragma unroll
            for (int np = 2; np < 4; np++) {
                uint32_t bh[4], bl[4];
                ldsm4(ka + np * 4352 + kb * 32, bh);
                ldsm4(ka + LO_OFF + np * 4352 + kb * 32, bl);
                mma_f16(sacc[2 * np],     ah, bh);
                mma_f16(sacc[2 * np + 1], ah, bh + 2);
                mma_f16(sacc[2 * np],     ah, bl);
                mma_f16(sacc[2 * np + 1], ah, bl + 2);
            }
        }

        // ============ softmax-B (nb 4..7) ============
        #pragma unroll
        for (int nb = 4; nb < 8; nb++) {
            float p[4];
            #pragma unroll
            for (int j = 0; j < 4; j++) {
                float pv = __expf(sacc[nb][j] * SM_SCALE);
                if (!allfull) {
                    int key = k0 + nb * 8 + 2 * tg + (j & 1);
                    int row = q0 + r0 + g + ((j >> 1) << 3);
                    bool ok = (key <= row) && (row - key < WIN);
                    pv = ok ? pv : 0.f;
                }
                p[j] = pv;
            }
            lsum0 += p[0] + p[1];
            lsum1 += p[2] + p[3];
            int kb2 = nb >> 1, hi = nb & 1;
            split2h(p[0], p[1], phi[kb2][hi * 2 + 0], plo[kb2][hi * 2 + 0]);
            split2h(p[2], p[3], phi[kb2][hi * 2 + 1], plo[kb2][hi * 2 + 1]);
        }

        // ============ PV-A: keys 0..31 (kb 0,1), fp16 3-term ============
        #pragma unroll
        for (int kb = 0; kb < 2; kb++) {
            #pragma unroll
            for (int npp = 0; npp < 4; npp++) {
                uint32_t vh0[4], vl0[4], vh1[4], vl1[4];
                ldsm4t(va + kb * 4352 + (2 * npp) * 32, vh0);
                ldsm4t(va + LO_OFF + kb * 4352 + (2 * npp) * 32, vl0);
                ldsm4t(va + kb * 4352 + (2 * npp + 1) * 32, vh1);
                ldsm4t(va + LO_OFF + kb * 4352 + (2 * npp + 1) * 32, vl1);
                float* o0 = oacc[4 * npp + 0];
                float* o1 = oacc[4 * npp + 1];
                float* o2 = oacc[4 * npp + 2];
                float* o3 = oacc[4 * npp + 3];
                mma_f16(o0, phi[kb], vh0);
                mma_f16(o1, phi[kb], vh0 + 2);
                mma_f16(o2, phi[kb], vh1);
                mma_f16(o3, phi[kb], vh1 + 2);
                mma_f16(o0, phi[kb], vl0);
                mma_f16(o1, phi[kb], vl0 + 2);
                mma_f16(o2, phi[kb], vl1);
                mma_f16(o3, phi[kb], vl1 + 2);
                mma_f16(o0, plo[kb], vh0);
                mma_f16(o1, plo[kb], vh0 + 2);
                mma_f16(o2, plo[kb], vh1);
                mma_f16(o3, plo[kb], vh1 + 2);
            }
        }
        // ============ PV-B: keys 32..63 (kb 2,3) ============
        #pragma unroll
        for (int kb = 2; kb < 4; kb++) {
            #pragma unroll
            for (int npp = 0; npp < 4; npp++) {
                uint32_t vh0[4], vl0[4], vh1[4], vl1[4];
                ldsm4t(va + kb * 4352 + (2 * npp) * 32, vh0);
                ldsm4t(va + LO_OFF + kb * 4352 + (2 * npp) * 32, vl0);
                ldsm4t(va + kb * 4352 + (2 * npp + 1) * 32, vh1);
                ldsm4t(va + LO_OFF + kb * 4352 + (2 * npp + 1) * 32, vl1);
                float* o0 = oacc[4 * npp + 0];
                float* o1 = oacc[4 * npp + 1];
                float* o2 = oacc[4 * npp + 2];
                float* o3 = oacc[4 * npp + 3];
                mma_f16(o0, phi[kb], vh0);
                mma_f16(o1, phi[kb], vh0 + 2);
                mma_f16(o2, phi[kb], vh1);
                mma_f16(o3, phi[kb], vh1 + 2);
                mma_f16(o0, phi[kb], vl0);
                mma_f16(o1, phi[kb], vl0 + 2);
                mma_f16(o2, phi[kb], vl1);
                mma_f16(o3, phi[kb], vl1 + 2);
                mma_f16(o0, plo[kb], vh0);
                mma_f16(o1, plo[kb], vh0 + 2);
                mma_f16(o2, plo[kb], vh1);
                mma_f16(o3, plo[kb], vh1 + 2);
            }
        }
        __syncthreads();
    }

    // ---- normalize + store ----
    lsum0 += __shfl_xor_sync(0xffffffffu, lsum0, 1);
    lsum0 += __shfl_xor_sync(0xffffffffu, lsum0, 2);
    lsum1 += __shfl_xor_sync(0xffffffffu, lsum1, 1);
    lsum1 += __shfl_xor_sync(0xffffffffu, lsum1, 2);
    const float inv0 = 1.f / lsum0;
    const float inv1 = 1.f / lsum1;

    const int row0 = q0 + r0 + g;
    float* o0 = Og + ((size_t)b * SQ + row0) * (NH * HD) + (size_t)h * HD;
    float* o1 = o0 + 8 * (size_t)(NH * HD);
    #pragma unroll
    for (int nb = 0; nb < 16; nb++) {
        int col = nb * 8 + 2 * tg;
        *(float2*)(o0 + col) = make_float2(oacc[nb][0] * inv0, oacc[nb][1] * inv0);
        *(float2*)(o1 + col) = make_float2(oacc[nb][2] * inv1, oacc[nb][3] * inv1);
    }
}

extern "C" void kernel_launch(void* const* d_in, const int* in_sizes, int n_in,
                              void* d_out, int out_size)
{
    const float* Q = (const float*)d_in[0];
    const float* K = (const float*)d_in[1];
    const float* V = (const float*)d_in[2];
    float* O = (float*)d_out;

    prep_kv<<<KVELEMS / 4 / 256, 256>>>(K, V);

    cudaFuncSetAttribute(attn_hmma, cudaFuncAttributeMaxDynamicSharedMemorySize, SMEM_BYTES);
    dim3 grid(SQ / BM, NH, NBATCH);
    attn_hmma<<<grid, THREADS, SMEM_BYTES>>>(Q, O);
}

// round 14
// speedup vs baseline: 1.2830x; 1.1653x over previous
#include <cuda_runtime.h>
#include <cuda_fp16.h>
#include <cstdint>

#define NH 32
#define NKV 8
#define SQ 2048
#define NBATCH 2
#define WIN 1024
#define SM_SCALE 0.08838834764831845f
#define BM 64
#define BN 64
#define HD 128
#define THREADS 128

// ---- fp16 hi/lo scratch (filled by prep kernel once per launch) ----
#define KVELEMS (NBATCH * NKV * SQ * HD)
__device__ __align__(16) uint16_t KHIg[KVELEMS];
__device__ __align__(16) uint16_t KLOg[KVELEMS];
__device__ __align__(16) uint16_t VHIg[KVELEMS];
__device__ __align__(16) uint16_t VLOg[KVELEMS];

// smem layout (bytes): Q hi static; single K/V hi/lo buffer (2 CTAs/SM overlap)
#define QSTR 136
#define KSTR 136
#define VSTR 136
#define QHI_B 0
#define QREG  (BM * QSTR * 2)                  // 17408
#define ARRB  (BN * KSTR * 2)                  // 17408 per array
#define KHI_O QREG
#define VHI_O (QREG + 2 * ARRB)
#define LO_OFF ARRB
#define SMEM_BYTES (QREG + 4 * ARRB + 16)      // 87056 -> 2 CTAs/SM

__device__ __forceinline__ uint32_t smaddr(const void* p) {
    uint32_t a;
    asm("{ .reg .u64 t; cvta.to.shared.u64 t, %1; cvt.u32.u64 %0, t; }" : "=r"(a) : "l"(p));
    return a;
}
__device__ __forceinline__ uint32_t packh2(float f0, float f1) {
    __half2 h = __floats2half2_rn(f0, f1);
    return *(uint32_t*)&h;
}
__device__ __forceinline__ void split2h(float f0, float f1, uint32_t& hi2, uint32_t& lo2) {
    __half2 h = __floats2half2_rn(f0, f1);
    hi2 = *(uint32_t*)&h;
    float2 back = __half22float2(h);
    __half2 l = __floats2half2_rn(f0 - back.x, f1 - back.y);
    lo2 = *(uint32_t*)&l;
}
__device__ __forceinline__ void ldsm4(uint32_t a, uint32_t* r) {
    asm volatile("ldmatrix.sync.aligned.m8n8.x4.shared.b16 {%0,%1,%2,%3}, [%4];"
        : "=r"(r[0]), "=r"(r[1]), "=r"(r[2]), "=r"(r[3]) : "r"(a));
}
__device__ __forceinline__ void ldsm4t(uint32_t a, uint32_t* r) {
    asm volatile("ldmatrix.sync.aligned.m8n8.x4.trans.shared.b16 {%0,%1,%2,%3}, [%4];"
        : "=r"(r[0]), "=r"(r[1]), "=r"(r[2]), "=r"(r[3]) : "r"(a));
}
__device__ __forceinline__ void mma_f16(float* c, const uint32_t* a, const uint32_t* b) {
    asm volatile("mma.sync.aligned.m16n8k16.row.col.f32.f16.f16.f32 "
        "{%0,%1,%2,%3}, {%4,%5,%6,%7}, {%8,%9}, {%0,%1,%2,%3};"
        : "+f"(c[0]), "+f"(c[1]), "+f"(c[2]), "+f"(c[3])
        : "r"(a[0]), "r"(a[1]), "r"(a[2]), "r"(a[3]), "r"(b[0]), "r"(b[1]));
}
__device__ __forceinline__ void cpa16(uint32_t saddr, const void* gaddr) {
    asm volatile("cp.async.cg.shared.global [%0], [%1], 16;" :: "r"(saddr), "l"(gaddr));
}

// ---- prep: fp32 K/V -> fp16 hi/lo scratch, [b][hk][s][d] layout ----
__global__ __launch_bounds__(256)
void prep_kv(const float* __restrict__ Kg, const float* __restrict__ Vg)
{
    int i = blockIdx.x * blockDim.x + threadIdx.x;
    int d4 = (i & 31) << 2;
    int hk = (i >> 5) & 7;
    int s  = (i >> 8) & 2047;
    int b  = i >> 19;
    size_t in  = ((size_t)(b * SQ + s)) * (NKV * HD) + hk * HD + d4;
    size_t out = (((size_t)(b * NKV + hk)) * SQ + s) * HD + d4;

    float4 v = *(const float4*)(Kg + in);
    uint32_t h01, l01, h23, l23;
    split2h(v.x, v.y, h01, l01);
    split2h(v.z, v.w, h23, l23);
    *(uint2*)&KHIg[out] = make_uint2(h01, h23);
    *(uint2*)&KLOg[out] = make_uint2(l01, l23);

    float4 w = *(const float4*)(Vg + in);
    split2h(w.x, w.y, h01, l01);
    split2h(w.z, w.w, h23, l23);
    *(uint2*)&VHIg[out] = make_uint2(h01, h23);
    *(uint2*)&VLOg[out] = make_uint2(l01, l23);
}

// issue 16B cp.async chunks for one 64-row KV tile (all 4 arrays); 128 threads
__device__ __forceinline__ void issue_tile(uint32_t sb, int tid, size_t kvrow0)
{
    const int ch8 = (tid & 15) * 8;
    #pragma unroll
    for (int i = 0; i < 32; i++) {
        const int arr = i >> 3;                    // 0..3
        const int r = (i & 7) * 8 + (tid >> 4);    // 0..63
        const uint16_t* gb = (arr == 0) ? KHIg : (arr == 1) ? KLOg
                           : (arr == 2) ? VHIg : VLOg;
        const void* g = gb + (kvrow0 + r) * HD + ch8;
        uint32_t s = sb + KHI_O + (uint32_t)arr * ARRB + (uint32_t)(r * KSTR + ch8) * 2u;
        cpa16(s, g);
    }
}

__global__ __launch_bounds__(THREADS, 2)
void attn_hmma(const float* __restrict__ Qg, float* __restrict__ Og)
{
    extern __shared__ __align__(16) char smch[];
    const uint32_t sb = smaddr(smch);

    const int tid = threadIdx.x;
    const int wid = tid >> 5, lane = tid & 31;
    const int g = lane >> 2, tg = lane & 3;
    const int r0 = wid * 16;

    const int qt = blockIdx.x, h = blockIdx.y, b = blockIdx.z;
    const int hk = h >> 2;
    const int q0 = qt * BM;

    const float* Qb = Qg + ((size_t)b * SQ) * (NH * HD) + (size_t)h * HD;
    const size_t kvbase = ((size_t)(b * NKV + hk)) * SQ;

    // ---- Q tile (64x128) -> smem (fp16 hi only) ----
    #pragma unroll
    for (int i = 0; i < 16; i++) {
        int c = tid + i * THREADS;
        int r = c >> 5, d4 = (c & 31) << 2;
        float4 v = *(const float4*)(Qb + (size_t)(q0 + r) * (NH * HD) + d4);
        uint32_t h01 = packh2(v.x, v.y);
        uint32_t h23 = packh2(v.z, v.w);
        *(uint2*)(smch + QHI_B + (r * QSTR + d4) * 2) = make_uint2(h01, h23);
    }
    __syncthreads();

    // ---- hoist Q fragments into registers (reused every tile) ----
    const uint32_t qa = sb + QHI_B + ((r0 + (lane & 15)) * QSTR + ((lane >> 4) << 3)) * 2;
    uint32_t ahold[8][4];
    #pragma unroll
    for (int kb = 0; kb < 8; kb++)
        ldsm4(qa + kb * 32, ahold[kb]);

    const uint32_t ka_rel = (uint32_t)((((lane & 7) + ((lane >> 4) & 1) * 8) * KSTR
                                        + (((lane >> 3) & 1) << 3)) * 2);
    const uint32_t va_rel = (uint32_t)((lane & 15) * (VSTR * 2) + (((lane >> 4) & 1) << 4));
    const uint32_t ka = sb + KHI_O + ka_rel;
    const uint32_t va = sb + VHI_O + va_rel;

    float oacc[16][4];
    #pragma unroll
    for (int nb = 0; nb < 16; nb++)
        #pragma unroll
        for (int j = 0; j < 4; j++) oacc[nb][j] = 0.f;
    float lsum0 = 0.f, lsum1 = 0.f;

    int lo_k = q0 - (WIN - 1); if (lo_k < 0) lo_k = 0;
    const int t0 = lo_k >> 6;
    const int t1 = (q0 + BM - 1) >> 6;

    for (int t = t0; t <= t1; ++t) {
        const int k0 = t << 6;

        // single-buffer load (previous compute finished at loop-end sync)
        issue_tile(sb, tid, kvbase + ((size_t)t << 6));
        asm volatile("cp.async.commit_group;" ::: "memory");
        asm volatile("cp.async.wait_group 0;" ::: "memory");
        __syncthreads();

        const bool allfull = (k0 + BN - 1 <= q0 + r0) && ((q0 + r0 + 15) - k0 < WIN);

        float sacc[8][4];
        #pragma unroll
        for (int nb = 0; nb < 8; nb++)
            #pragma unroll
            for (int j = 0; j < 4; j++) sacc[nb][j] = 0.f;

        uint32_t phi[4][4], plo[4][4];

        // ============ QK-A: keys 0..31 (np 0,1), fp16 2-term ============
        #pragma unroll
        for (int kb = 0; kb < 8; kb++) {
            #pragma unroll
            for (int np = 0; np < 2; np++) {
                uint32_t bh[4], bl[4];
                ldsm4(ka + np * 4352 + kb * 32, bh);
                ldsm4(ka + LO_OFF + np * 4352 + kb * 32, bl);
                mma_f16(sacc[2 * np],     ahold[kb], bh);
                mma_f16(sacc[2 * np + 1], ahold[kb], bh + 2);
                mma_f16(sacc[2 * np],     ahold[kb], bl);
                mma_f16(sacc[2 * np + 1], ahold[kb], bl + 2);
            }
        }

        // ============ softmax-A (nb 0..3) ============
        #pragma unroll
        for (int nb = 0; nb < 4; nb++) {
            float p[4];
            #pragma unroll
            for (int j = 0; j < 4; j++) {
                float pv = __expf(sacc[nb][j] * SM_SCALE);
                if (!allfull) {
                    int key = k0 + nb * 8 + 2 * tg + (j & 1);
                    int row = q0 + r0 + g + ((j >> 1) << 3);
                    bool ok = (key <= row) && (row - key < WIN);
                    pv = ok ? pv : 0.f;
                }
                p[j] = pv;
            }
            lsum0 += p[0] + p[1];
            lsum1 += p[2] + p[3];
            int kb2 = nb >> 1, hi = nb & 1;
            split2h(p[0], p[1], phi[kb2][hi * 2 + 0], plo[kb2][hi * 2 + 0]);
            split2h(p[2], p[3], phi[kb2][hi * 2 + 1], plo[kb2][hi * 2 + 1]);
        }

        // ============ QK-B: keys 32..63 (np 2,3) ============
        #pragma unroll
        for (int kb = 0; kb < 8; kb++) {
            #pragma unroll
            for (int np = 2; np < 4; np++) {
                uint32_t bh[4], bl[4];
                ldsm4(ka + np * 4352 + kb * 32, bh);
                ldsm4(ka + LO_OFF + np * 4352 + kb * 32, bl);
                mma_f16(sacc[2 * np],     ahold[kb], bh);
                mma_f16(sacc[2 * np + 1], ahold[kb], bh + 2);
                mma_f16(sacc[2 * np],     ahold[kb], bl);
                mma_f16(sacc[2 * np + 1], ahold[kb], bl + 2);
            }
        }

        // ============ softmax-B (nb 4..7) ============
        #pragma unroll
        for (int nb = 4; nb < 8; nb++) {
            float p[4];
            #pragma unroll
            for (int j = 0; j < 4; j++) {
                float pv = __expf(sacc[nb][j] * SM_SCALE);
                if (!allfull) {
                    int key = k0 + nb * 8 + 2 * tg + (j & 1);
                    int row = q0 + r0 + g + ((j >> 1) << 3);
                    bool ok = (key <= row) && (row - key < WIN);
                    pv = ok ? pv : 0.f;
                }
                p[j] = pv;
            }
            lsum0 += p[0] + p[1];
            lsum1 += p[2] + p[3];
            int kb2 = nb >> 1, hi = nb & 1;
            split2h(p[0], p[1], phi[kb2][hi * 2 + 0], plo[kb2][hi * 2 + 0]);
            split2h(p[2], p[3], phi[kb2][hi * 2 + 1], plo[kb2][hi * 2 + 1]);
        }

        // ============ PV: fp16 3-term ============
        #pragma unroll
        for (int kb = 0; kb < 4; kb++) {
            #pragma unroll
            for (int npp = 0; npp < 4; npp++) {
                uint32_t vh0[4], vl0[4], vh1[4], vl1[4];
                ldsm4t(va + kb * 4352 + (2 * npp) * 32, vh0);
                ldsm4t(va + LO_OFF + kb * 4352 + (2 * npp) * 32, vl0);
                ldsm4t(va + kb * 4352 + (2 * npp + 1) * 32, vh1);
                ldsm4t(va + LO_OFF + kb * 4352 + (2 * npp + 1) * 32, vl1);
                float* o0 = oacc[4 * npp + 0];
                float* o1 = oacc[4 * npp + 1];
                float* o2 = oacc[4 * npp + 2];
                float* o3 = oacc[4 * npp + 3];
                mma_f16(o0, phi[kb], vh0);
                mma_f16(o1, phi[kb], vh0 + 2);
                mma_f16(o2, phi[kb], vh1);
                mma_f16(o3, phi[kb], vh1 + 2);
                mma_f16(o0, phi[kb], vl0);
                mma_f16(o1, phi[kb], vl0 + 2);
                mma_f16(o2, phi[kb], vl1);
                mma_f16(o3, phi[kb], vl1 + 2);
                mma_f16(o0, plo[kb], vh0);
                mma_f16(o1, plo[kb], vh0 + 2);
                mma_f16(o2, plo[kb], vh1);
                mma_f16(o3, plo[kb], vh1 + 2);
            }
        }
        __syncthreads();   // compute done before next tile overwrites buffer
    }

    // ---- normalize + store ----
    lsum0 += __shfl_xor_sync(0xffffffffu, lsum0, 1);
    lsum0 += __shfl_xor_sync(0xffffffffu, lsum0, 2);
    lsum1 += __shfl_xor_sync(0xffffffffu, lsum1, 1);
    lsum1 += __shfl_xor_sync(0xffffffffu, lsum1, 2);
    const float inv0 = 1.f / lsum0;
    const float inv1 = 1.f / lsum1;

    const int row0 = q0 + r0 + g;
    float* o0 = Og + ((size_t)b * SQ + row0) * (NH * HD) + (size_t)h * HD;
    float* o1 = o0 + 8 * (size_t)(NH * HD);
    #pragma unroll
    for (int nb = 0; nb < 16; nb++) {
        int col = nb * 8 + 2 * tg;
        *(float2*)(o0 + col) = make_float2(oacc[nb][0] * inv0, oacc[nb][1] * inv0);
        *(float2*)(o1 + col) = make_float2(oacc[nb][2] * inv1, oacc[nb][3] * inv1);
    }
}

extern "C" void kernel_launch(void* const* d_in, const int* in_sizes, int n_in,
                              void* d_out, int out_size)
{
    const float* Q = (const float*)d_in[0];
    const float* K = (const float*)d_in[1];
    const float* V = (const float*)d_in[2];
    float* O = (float*)d_out;

    prep_kv<<<KVELEMS / 4 / 256, 256>>>(K, V);

    cudaFuncSetAttribute(attn_hmma, cudaFuncAttributeMaxDynamicSharedMemorySize, SMEM_BYTES);
    dim3 grid(SQ / BM, NH, NBATCH);
    attn_hmma<<<grid, THREADS, SMEM_BYTES>>>(Q, O);
}

// round 15
// speedup vs baseline: 1.6926x; 1.3193x over previous
#include <cuda_runtime.h>
#include <cuda_fp16.h>
#include <cstdint>

#define NH 32
#define NKV 8
#define SQ 2048
#define NBATCH 2
#define WIN 1024
#define SM_SCALE 0.08838834764831845f
#define BM 64
#define BN 64
#define HD 128
#define THREADS 128

// ---- fp16 hi/lo scratch (filled by prep kernel once per launch) ----
#define KVELEMS (NBATCH * NKV * SQ * HD)
__device__ __align__(16) uint16_t KHIg[KVELEMS];
__device__ __align__(16) uint16_t KLOg[KVELEMS];
__device__ __align__(16) uint16_t VHIg[KVELEMS];

// smem layout (bytes): Q hi static; single {Khi,Klo,Vhi} buffer
#define QSTR 136
#define KSTR 136
#define VSTR 136
#define QHI_B 0
#define QREG  (BM * QSTR * 2)                  // 17408
#define ARRB  (BN * KSTR * 2)                  // 17408 per array
#define KHI_O QREG
#define VHI_O (QREG + 2 * ARRB)
#define LO_OFF ARRB
#define SMEM_BYTES (QREG + 3 * ARRB + 16)      // 69648 -> smem allows 3 CTAs/SM

__device__ __forceinline__ uint32_t smaddr(const void* p) {
    uint32_t a;
    asm("{ .reg .u64 t; cvta.to.shared.u64 t, %1; cvt.u32.u64 %0, t; }" : "=r"(a) : "l"(p));
    return a;
}
__device__ __forceinline__ uint32_t packh2(float f0, float f1) {
    __half2 h = __floats2half2_rn(f0, f1);
    return *(uint32_t*)&h;
}
__device__ __forceinline__ void split2h(float f0, float f1, uint32_t& hi2, uint32_t& lo2) {
    __half2 h = __floats2half2_rn(f0, f1);
    hi2 = *(uint32_t*)&h;
    float2 back = __half22float2(h);
    __half2 l = __floats2half2_rn(f0 - back.x, f1 - back.y);
    lo2 = *(uint32_t*)&l;
}
__device__ __forceinline__ void ldsm4(uint32_t a, uint32_t* r) {
    asm volatile("ldmatrix.sync.aligned.m8n8.x4.shared.b16 {%0,%1,%2,%3}, [%4];"
        : "=r"(r[0]), "=r"(r[1]), "=r"(r[2]), "=r"(r[3]) : "r"(a));
}
__device__ __forceinline__ void ldsm4t(uint32_t a, uint32_t* r) {
    asm volatile("ldmatrix.sync.aligned.m8n8.x4.trans.shared.b16 {%0,%1,%2,%3}, [%4];"
        : "=r"(r[0]), "=r"(r[1]), "=r"(r[2]), "=r"(r[3]) : "r"(a));
}
__device__ __forceinline__ void mma_f16(float* c, const uint32_t* a, const uint32_t* b) {
    asm volatile("mma.sync.aligned.m16n8k16.row.col.f32.f16.f16.f32 "
        "{%0,%1,%2,%3}, {%4,%5,%6,%7}, {%8,%9}, {%0,%1,%2,%3};"
        : "+f"(c[0]), "+f"(c[1]), "+f"(c[2]), "+f"(c[3])
        : "r"(a[0]), "r"(a[1]), "r"(a[2]), "r"(a[3]), "r"(b[0]), "r"(b[1]));
}
__device__ __forceinline__ void cpa16(uint32_t saddr, const void* gaddr) {
    asm volatile("cp.async.cg.shared.global [%0], [%1], 16;" :: "r"(saddr), "l"(gaddr));
}

// ---- prep: fp32 K/V -> fp16 scratch (K hi/lo, V hi), [b][hk][s][d] ----
__global__ __launch_bounds__(256)
void prep_kv(const float* __restrict__ Kg, const float* __restrict__ Vg)
{
    int i = blockIdx.x * blockDim.x + threadIdx.x;
    int d4 = (i & 31) << 2;
    int hk = (i >> 5) & 7;
    int s  = (i >> 8) & 2047;
    int b  = i >> 19;
    size_t in  = ((size_t)(b * SQ + s)) * (NKV * HD) + hk * HD + d4;
    size_t out = (((size_t)(b * NKV + hk)) * SQ + s) * HD + d4;

    float4 v = *(const float4*)(Kg + in);
    uint32_t h01, l01, h23, l23;
    split2h(v.x, v.y, h01, l01);
    split2h(v.z, v.w, h23, l23);
    *(uint2*)&KHIg[out] = make_uint2(h01, h23);
    *(uint2*)&KLOg[out] = make_uint2(l01, l23);

    float4 w = *(const float4*)(Vg + in);
    uint32_t wh01 = packh2(w.x, w.y);
    uint32_t wh23 = packh2(w.z, w.w);
    *(uint2*)&VHIg[out] = make_uint2(wh01, wh23);
}

// issue 16B cp.async chunks for one 64-row KV tile (Khi,Klo,Vhi); 128 threads
__device__ __forceinline__ void issue_tile(uint32_t sb, int tid, size_t kvrow0)
{
    const int ch8 = (tid & 15) * 8;
    #pragma unroll
    for (int i = 0; i < 24; i++) {
        const int arr = i >> 3;                    // 0..2
        const int r = (i & 7) * 8 + (tid >> 4);    // 0..63
        const uint16_t* gb = (arr == 0) ? KHIg : (arr == 1) ? KLOg : VHIg;
        const void* g = gb + (kvrow0 + r) * HD + ch8;
        uint32_t s = sb + KHI_O + (uint32_t)arr * ARRB + (uint32_t)(r * KSTR + ch8) * 2u;
        cpa16(s, g);
    }
}

__global__ __launch_bounds__(THREADS, 2)
void attn_hmma(const float* __restrict__ Qg, float* __restrict__ Og)
{
    extern __shared__ __align__(16) char smch[];
    const uint32_t sb = smaddr(smch);

    const int tid = threadIdx.x;
    const int wid = tid >> 5, lane = tid & 31;
    const int g = lane >> 2, tg = lane & 3;
    const int r0 = wid * 16;

    const int qt = blockIdx.x, h = blockIdx.y, b = blockIdx.z;
    const int hk = h >> 2;
    const int q0 = qt * BM;

    const float* Qb = Qg + ((size_t)b * SQ) * (NH * HD) + (size_t)h * HD;
    const size_t kvbase = ((size_t)(b * NKV + hk)) * SQ;

    // ---- Q tile (64x128) -> smem (fp16 hi only) ----
    #pragma unroll
    for (int i = 0; i < 16; i++) {
        int c = tid + i * THREADS;
        int r = c >> 5, d4 = (c & 31) << 2;
        float4 v = *(const float4*)(Qb + (size_t)(q0 + r) * (NH * HD) + d4);
        uint32_t h01 = packh2(v.x, v.y);
        uint32_t h23 = packh2(v.z, v.w);
        *(uint2*)(smch + QHI_B + (r * QSTR + d4) * 2) = make_uint2(h01, h23);
    }
    __syncthreads();

    // ---- hoist Q fragments into registers (reused every tile) ----
    const uint32_t qa = sb + QHI_B + ((r0 + (lane & 15)) * QSTR + ((lane >> 4) << 3)) * 2;
    uint32_t ahold[8][4];
    #pragma unroll
    for (int kb = 0; kb < 8; kb++)
        ldsm4(qa + kb * 32, ahold[kb]);

    const uint32_t ka_rel = (uint32_t)((((lane & 7) + ((lane >> 4) & 1) * 8) * KSTR
                                        + (((lane >> 3) & 1) << 3)) * 2);
    const uint32_t va_rel = (uint32_t)((lane & 15) * (VSTR * 2) + (((lane >> 4) & 1) << 4));
    const uint32_t ka = sb + KHI_O + ka_rel;
    const uint32_t va = sb + VHI_O + va_rel;

    float oacc[16][4];
    #pragma unroll
    for (int nb = 0; nb < 16; nb++)
        #pragma unroll
        for (int j = 0; j < 4; j++) oacc[nb][j] = 0.f;
    float lsum0 = 0.f, lsum1 = 0.f;

    int lo_k = q0 - (WIN - 1); if (lo_k < 0) lo_k = 0;
    const int t0 = lo_k >> 6;
    const int t1 = (q0 + BM - 1) >> 6;

    for (int t = t0; t <= t1; ++t) {
        const int k0 = t << 6;

        // single-buffer load (peer CTA covers this latency)
        issue_tile(sb, tid, kvbase + ((size_t)t << 6));
        asm volatile("cp.async.commit_group;" ::: "memory");
        asm volatile("cp.async.wait_group 0;" ::: "memory");
        __syncthreads();

        const bool allfull = (k0 + BN - 1 <= q0 + r0) && ((q0 + r0 + 15) - k0 < WIN);

        float sacc[8][4];
        #pragma unroll
        for (int nb = 0; nb < 8; nb++)
            #pragma unroll
            for (int j = 0; j < 4; j++) sacc[nb][j] = 0.f;

        // ============ QK^T: fp16 2-term (q_hi·k_hi + q_hi·k_lo) ============
        #pragma unroll
        for (int kb = 0; kb < 8; kb++) {
            #pragma unroll
            for (int np = 0; np < 4; np++) {
                uint32_t bh[4], bl[4];
                ldsm4(ka + np * 4352 + kb * 32, bh);
                ldsm4(ka + LO_OFF + np * 4352 + kb * 32, bl);
                mma_f16(sacc[2 * np],     ahold[kb], bh);
                mma_f16(sacc[2 * np + 1], ahold[kb], bh + 2);
                mma_f16(sacc[2 * np],     ahold[kb], bl);
                mma_f16(sacc[2 * np + 1], ahold[kb], bl + 2);
            }
        }

        // ============ softmax -> P fp16 fragments (hi only) ============
        uint32_t phi[4][4];
        #pragma unroll
        for (int nb = 0; nb < 8; nb++) {
            float p[4];
            #pragma unroll
            for (int j = 0; j < 4; j++) {
                float pv = __expf(sacc[nb][j] * SM_SCALE);
                if (!allfull) {
                    int key = k0 + nb * 8 + 2 * tg + (j & 1);
                    int row = q0 + r0 + g + ((j >> 1) << 3);
                    bool ok = (key <= row) && (row - key < WIN);
                    pv = ok ? pv : 0.f;
                }
                p[j] = pv;
            }
            lsum0 += p[0] + p[1];
            lsum1 += p[2] + p[3];
            int kb2 = nb >> 1, hi = nb & 1;
            phi[kb2][hi * 2 + 0] = packh2(p[0], p[1]);
            phi[kb2][hi * 2 + 1] = packh2(p[2], p[3]);
        }

        // ============ PV: fp16 1-term (p_hi·v_hi) ============
        #pragma unroll
        for (int kb = 0; kb < 4; kb++) {
            #pragma unroll
            for (int npp = 0; npp < 4; npp++) {
                uint32_t vh0[4], vh1[4];
                ldsm4t(va + kb * 4352 + (2 * npp) * 32, vh0);
                ldsm4t(va + kb * 4352 + (2 * npp + 1) * 32, vh1);
                mma_f16(oacc[4 * npp + 0], phi[kb], vh0);
                mma_f16(oacc[4 * npp + 1], phi[kb], vh0 + 2);
                mma_f16(oacc[4 * npp + 2], phi[kb], vh1);
                mma_f16(oacc[4 * npp + 3], phi[kb], vh1 + 2);
            }
        }
        __syncthreads();   // compute done before next tile overwrites buffer
    }

    // ---- normalize + store ----
    lsum0 += __shfl_xor_sync(0xffffffffu, lsum0, 1);
    lsum0 += __shfl_xor_sync(0xffffffffu, lsum0, 2);
    lsum1 += __shfl_xor_sync(0xffffffffu, lsum1, 1);
    lsum1 += __shfl_xor_sync(0xffffffffu, lsum1, 2);
    const float inv0 = 1.f / lsum0;
    const float inv1 = 1.f / lsum1;

    const int row0 = q0 + r0 + g;
    float* o0 = Og + ((size_t)b * SQ + row0) * (NH * HD) + (size_t)h * HD;
    float* o1 = o0 + 8 * (size_t)(NH * HD);
    #pragma unroll
    for (int nb = 0; nb < 16; nb++) {
        int col = nb * 8 + 2 * tg;
        *(float2*)(o0 + col) = make_float2(oacc[nb][0] * inv0, oacc[nb][1] * inv0);
        *(float2*)(o1 + col) = make_float2(oacc[nb][2] * inv1, oacc[nb][3] * inv1);
    }
}

extern "C" void kernel_launch(void* const* d_in, const int* in_sizes, int n_in,
                              void* d_out, int out_size)
{
    const float* Q = (const float*)d_in[0];
    const float* K = (const float*)d_in[1];
    const float* V = (const float*)d_in[2];
    float* O = (float*)d_out;

    prep_kv<<<KVELEMS / 4 / 256, 256>>>(K, V);

    cudaFuncSetAttribute(attn_hmma, cudaFuncAttributeMaxDynamicSharedMemorySize, SMEM_BYTES);
    dim3 grid(SQ / BM, NH, NBATCH);
    attn_hmma<<<grid, THREADS, SMEM_BYTES>>>(Q, O);
}

// round 17
// speedup vs baseline: 2.3403x; 1.3826x over previous
#include <cuda_runtime.h>
#include <cuda_fp16.h>
#include <cstdint>

#define NH 32
#define NKV 8
#define SQ 2048
#define NBATCH 2
#define WIN 1024
#define SM_SCALE 0.08838834764831845f
#define BM 64
#define BN 64
#define HD 128
#define THREADS 128

// ---- fp16 scratch (filled by prep kernel once per launch) ----
#define KVELEMS (NBATCH * NKV * SQ * HD)
__device__ __align__(16) uint16_t KHIg[KVELEMS];
__device__ __align__(16) uint16_t VHIg[KVELEMS];

// smem layout (bytes): Q hi static; single {Khi,Vhi} buffer
#define QSTR 136
#define KSTR 136
#define VSTR 136
#define QHI_B 0
#define QREG  (BM * QSTR * 2)                  // 17408
#define ARRB  (BN * KSTR * 2)                  // 17408 per array
#define KHI_O QREG
#define VHI_O (QREG + ARRB)
#define SMEM_BYTES (QREG + 2 * ARRB + 16)      // 52240 -> 3 CTAs/SM (156KB)

__device__ __forceinline__ uint32_t smaddr(const void* p) {
    uint32_t a;
    asm("{ .reg .u64 t; cvta.to.shared.u64 t, %1; cvt.u32.u64 %0, t; }" : "=r"(a) : "l"(p));
    return a;
}
__device__ __forceinline__ uint32_t packh2(float f0, float f1) {
    __half2 h = __floats2half2_rn(f0, f1);
    return *(uint32_t*)&h;
}
__device__ __forceinline__ void ldsm4(uint32_t a, uint32_t* r) {
    asm volatile("ldmatrix.sync.aligned.m8n8.x4.shared.b16 {%0,%1,%2,%3}, [%4];"
        : "=r"(r[0]), "=r"(r[1]), "=r"(r[2]), "=r"(r[3]) : "r"(a));
}
__device__ __forceinline__ void ldsm4t(uint32_t a, uint32_t* r) {
    asm volatile("ldmatrix.sync.aligned.m8n8.x4.trans.shared.b16 {%0,%1,%2,%3}, [%4];"
        : "=r"(r[0]), "=r"(r[1]), "=r"(r[2]), "=r"(r[3]) : "r"(a));
}
__device__ __forceinline__ void mma_f16(float* c, const uint32_t* a, const uint32_t* b) {
    asm volatile("mma.sync.aligned.m16n8k16.row.col.f32.f16.f16.f32 "
        "{%0,%1,%2,%3}, {%4,%5,%6,%7}, {%8,%9}, {%0,%1,%2,%3};"
        : "+f"(c[0]), "+f"(c[1]), "+f"(c[2]), "+f"(c[3])
        : "r"(a[0]), "r"(a[1]), "r"(a[2]), "r"(a[3]), "r"(b[0]), "r"(b[1]));
}
__device__ __forceinline__ void cpa16(uint32_t saddr, const void* gaddr) {
    asm volatile("cp.async.cg.shared.global [%0], [%1], 16;" :: "r"(saddr), "l"(gaddr));
}

// ---- prep: fp32 K/V -> fp16 scratch, [b][hk][s][d] layout ----
__global__ __launch_bounds__(256)
void prep_kv(const float* __restrict__ Kg, const float* __restrict__ Vg)
{
    int i = blockIdx.x * blockDim.x + threadIdx.x;
    int d4 = (i & 31) << 2;
    int hk = (i >> 5) & 7;
    int s  = (i >> 8) & 2047;
    int b  = i >> 19;
    size_t in  = ((size_t)(b * SQ + s)) * (NKV * HD) + hk * HD + d4;
    size_t out = (((size_t)(b * NKV + hk)) * SQ + s) * HD + d4;

    float4 v = *(const float4*)(Kg + in);
    *(uint2*)&KHIg[out] = make_uint2(packh2(v.x, v.y), packh2(v.z, v.w));

    float4 w = *(const float4*)(Vg + in);
    *(uint2*)&VHIg[out] = make_uint2(packh2(w.x, w.y), packh2(w.z, w.w));
}

// issue 16B cp.async chunks for one 64-row KV tile (Khi,Vhi); 128 threads
__device__ __forceinline__ void issue_tile(uint32_t sb, int tid, size_t kvrow0)
{
    const int ch8 = (tid & 15) * 8;
    #pragma unroll
    for (int i = 0; i < 16; i++) {
        const int arr = i >> 3;                    // 0..1
        const int r = (i & 7) * 8 + (tid >> 4);    // 0..63
        const uint16_t* gb = (arr == 0) ? KHIg : VHIg;
        const void* g = gb + (kvrow0 + r) * HD + ch8;
        uint32_t s = sb + KHI_O + (uint32_t)arr * ARRB + (uint32_t)(r * KSTR + ch8) * 2u;
        cpa16(s, g);
    }
}

__global__ __launch_bounds__(THREADS, 3)
void attn_hmma(const float* __restrict__ Qg, float* __restrict__ Og)
{
    extern __shared__ __align__(16) char smch[];
    const uint32_t sb = smaddr(smch);

    const int tid = threadIdx.x;
    const int wid = tid >> 5, lane = tid & 31;
    const int g = lane >> 2, tg = lane & 3;
    const int r0 = wid * 16;

    const int qt = blockIdx.x, h = blockIdx.y, b = blockIdx.z;
    const int hk = h >> 2;
    const int q0 = qt * BM;

    const float* Qb = Qg + ((size_t)b * SQ) * (NH * HD) + (size_t)h * HD;
    const size_t kvbase = ((size_t)(b * NKV + hk)) * SQ;

    // ---- Q tile (64x128) -> smem (fp16) ----
    #pragma unroll
    for (int i = 0; i < 16; i++) {
        int c = tid + i * THREADS;
        int r = c >> 5, d4 = (c & 31) << 2;
        float4 v = *(const float4*)(Qb + (size_t)(q0 + r) * (NH * HD) + d4);
        *(uint2*)(smch + QHI_B + (r * QSTR + d4) * 2) =
            make_uint2(packh2(v.x, v.y), packh2(v.z, v.w));
    }
    __syncthreads();

    // ---- hoist Q fragments into registers (reused every tile) ----
    const uint32_t qa = sb + QHI_B + ((r0 + (lane & 15)) * QSTR + ((lane >> 4) << 3)) * 2;
    uint32_t ahold[8][4];
    #pragma unroll
    for (int kb = 0; kb < 8; kb++)
        ldsm4(qa + kb * 32, ahold[kb]);

    const uint32_t ka_rel = (uint32_t)((((lane & 7) + ((lane >> 4) & 1) * 8) * KSTR
                                        + (((lane >> 3) & 1) << 3)) * 2);
    const uint32_t va_rel = (uint32_t)((lane & 15) * (VSTR * 2) + (((lane >> 4) & 1) << 4));
    const uint32_t ka = sb + KHI_O + ka_rel;
    const uint32_t va = sb + VHI_O + va_rel;

    float oacc[16][4];
    #pragma unroll
    for (int nb = 0; nb < 16; nb++)
        #pragma unroll
        for (int j = 0; j < 4; j++) oacc[nb][j] = 0.f;
    float lsum0 = 0.f, lsum1 = 0.f;

    int lo_k = q0 - (WIN - 1); if (lo_k < 0) lo_k = 0;
    const int t0 = lo_k >> 6;
    const int t1 = (q0 + BM - 1) >> 6;

    for (int t = t0; t <= t1; ++t) {
        const int k0 = t << 6;

        // single-buffer load (peer CTAs cover this latency)
        issue_tile(sb, tid, kvbase + ((size_t)t << 6));
        asm volatile("cp.async.commit_group;" ::: "memory");
        asm volatile("cp.async.wait_group 0;" ::: "memory");
        __syncthreads();

        const bool allfull = (k0 + BN - 1 <= q0 + r0) && ((q0 + r0 + 15) - k0 < WIN);

        float sacc[8][4];
        #pragma unroll
        for (int nb = 0; nb < 8; nb++)
            #pragma unroll
            for (int j = 0; j < 4; j++) sacc[nb][j] = 0.f;

        // ============ QK^T: fp16 1-term (q_hi·k_hi) ============
        #pragma unroll
        for (int kb = 0; kb < 8; kb++) {
            #pragma unroll
            for (int np = 0; np < 4; np++) {
                uint32_t bh[4];
                ldsm4(ka + np * 4352 + kb * 32, bh);
                mma_f16(sacc[2 * np],     ahold[kb], bh);
                mma_f16(sacc[2 * np + 1], ahold[kb], bh + 2);
            }
        }

        // ============ softmax -> P fp16 fragments ============
        uint32_t phi[4][4];
        #pragma unroll
        for (int nb = 0; nb < 8; nb++) {
            float p[4];
            #pragma unroll
            for (int j = 0; j < 4; j++) {
                float pv = __expf(sacc[nb][j] * SM_SCALE);
                if (!allfull) {
                    int key = k0 + nb * 8 + 2 * tg + (j & 1);
                    int row = q0 + r0 + g + ((j >> 1) << 3);
                    bool ok = (key <= row) && (row - key < WIN);
                    pv = ok ? pv : 0.f;
                }
                p[j] = pv;
            }
            lsum0 += p[0] + p[1];
            lsum1 += p[2] + p[3];
            int kb2 = nb >> 1, hi = nb & 1;
            phi[kb2][hi * 2 + 0] = packh2(p[0], p[1]);
            phi[kb2][hi * 2 + 1] = packh2(p[2], p[3]);
        }

        // ============ PV: fp16 1-term (p_hi·v_hi) ============
        #pragma unroll
        for (int kb = 0; kb < 4; kb++) {
            #pragma unroll
            for (int npp = 0; npp < 4; npp++) {
                uint32_t vh0[4], vh1[4];
                ldsm4t(va + kb * 4352 + (2 * npp) * 32, vh0);
                ldsm4t(va + kb * 4352 + (2 * npp + 1) * 32, vh1);
                mma_f16(oacc[4 * npp + 0], phi[kb], vh0);
                mma_f16(oacc[4 * npp + 1], phi[kb], vh0 + 2);
                mma_f16(oacc[4 * npp + 2], phi[kb], vh1);
                mma_f16(oacc[4 * npp + 3], phi[kb], vh1 + 2);
            }
        }
        __syncthreads();   // compute done before next tile overwrites buffer
    }

    // ---- normalize + store ----
    lsum0 += __shfl_xor_sync(0xffffffffu, lsum0, 1);
    lsum0 += __shfl_xor_sync(0xffffffffu, lsum0, 2);
    lsum1 += __shfl_xor_sync(0xffffffffu, lsum1, 1);
    lsum1 += __shfl_xor_sync(0xffffffffu, lsum1, 2);
    const float inv0 = 1.f / lsum0;
    const float inv1 = 1.f / lsum1;

    const int row0 = q0 + r0 + g;
    float* o0 = Og + ((size_t)b * SQ + row0) * (NH * HD) + (size_t)h * HD;
    float* o1 = o0 + 8 * (size_t)(NH * HD);
    #pragma unroll
    for (int nb = 0; nb < 16; nb++) {
        int col = nb * 8 + 2 * tg;
        *(float2*)(o0 + col) = make_float2(oacc[nb][0] * inv0, oacc[nb][1] * inv0);
        *(float2*)(o1 + col) = make_float2(oacc[nb][2] * inv1, oacc[nb][3] * inv1);
    }
}

extern "C" void kernel_launch(void* const* d_in, const int* in_sizes, int n_in,
                              void* d_out, int out_size)
{
    const float* Q = (const float*)d_in[0];
    const float* K = (const float*)d_in[1];
    const float* V = (const float*)d_in[2];
    float* O = (float*)d_out;

    prep_kv<<<KVELEMS / 4 / 256, 256>>>(K, V);

    cudaFuncSetAttribute(attn_hmma, cudaFuncAttributeMaxDynamicSharedMemorySize, SMEM_BYTES);
    dim3 grid(SQ / BM, NH, NBATCH);
    attn_hmma<<<grid, THREADS, SMEM_BYTES>>>(Q, O);
}